// round 3
// baseline (speedup 1.0000x reference)
#include <cuda_runtime.h>
#include <cuda_bf16.h>

// Scratch for projected x / y (relu(inp @ W^T + b)), 32 MB each.
static __device__ float g_xp[8388608];
static __device__ float g_yp[8388608];

// ---- packed f32x2 helpers (FFMA2 path: 2x fp32 FMA throughput on sm_103a) ----
__device__ __forceinline__ void fma2(unsigned long long &d, unsigned long long a, unsigned long long b){
    asm("fma.rn.f32x2 %0, %1, %2, %0;" : "+l"(d) : "l"(a), "l"(b));
}
__device__ __forceinline__ void mul2(unsigned long long &d, unsigned long long s){
    asm("mul.rn.f32x2 %0, %0, %1;" : "+l"(d) : "l"(s));
}
__device__ __forceinline__ float flo(unsigned long long v){ return __uint_as_float((unsigned int)v); }
__device__ __forceinline__ float fhi(unsigned long long v){ return __uint_as_float((unsigned int)(v >> 32)); }
__device__ __forceinline__ unsigned long long fdup(float f){
    unsigned int u = __float_as_uint(f);
    return ((unsigned long long)u << 32) | (unsigned long long)u;
}

// ============================================================================
// Projection: proj = relu(inp @ W^T + b).  Tile: 64 rows x 64 out-cols.
// grid.x: 0..1023 -> x rows, 1024..2047 -> y rows.  grid.y: column half.
// d-paired f32x2 accumulation (even/odd d partial sums -> zero packing cost).
// W tile in smem with XOR-swizzled float4 columns (conflict-free strided reads).
// ============================================================================
__global__ __launch_bounds__(256, 2) void proj_kernel(
    const float* __restrict__ x, const float* __restrict__ y,
    const float* __restrict__ W, const float* __restrict__ bias)
{
    extern __shared__ __align__(16) float smem[];
    float* sIn = smem;          // [64][128]
    float* sW  = smem + 8192;   // [64 h-rows][128 d], swizzled
    float* sB  = smem + 16384;  // [64]

    const int rt = blockIdx.x, gy = blockIdx.y;
    const int tid = threadIdx.x, tx = tid & 15, ty = tid >> 4;

    const float4* src;
    float* dst;
    if (rt < 1024){ src = (const float4*)(x + (size_t)rt * 8192);        dst = g_xp + (size_t)rt * 8192; }
    else          { src = (const float4*)(y + (size_t)(rt-1024) * 8192); dst = g_yp + (size_t)(rt-1024) * 8192; }
    const float4* w4 = (const float4*)(W + gy * 8192);

    for (int f = tid; f < 2048; f += 256){
        ((float4*)sIn)[f] = src[f];
        int h = f >> 5, d4 = f & 31;
        ((float4*)sW)[(h << 5) + (d4 ^ (h & 7))] = w4[f];
    }
    if (tid < 64) sB[tid] = bias[gy*64 + tid];
    __syncthreads();

    unsigned long long acc[4][4];
    #pragma unroll
    for (int i = 0; i < 4; i++)
        #pragma unroll
        for (int j = 0; j < 4; j++) acc[i][j] = 0ull;

    const int sw = tx & 7;   // (tx+16*hh)&7 == tx&7
    #pragma unroll 8
    for (int d4 = 0; d4 < 32; d4++){
        ulonglong2 av[4], wv[4];
        #pragma unroll
        for (int ii = 0; ii < 4; ii++)
            av[ii] = ((const ulonglong2*)sIn)[((ty + 16*ii) << 5) + d4];
        #pragma unroll
        for (int hh = 0; hh < 4; hh++)
            wv[hh] = ((const ulonglong2*)sW)[((tx + 16*hh) << 5) + (d4 ^ sw)];
        #pragma unroll
        for (int ii = 0; ii < 4; ii++)
            #pragma unroll
            for (int hh = 0; hh < 4; hh++){
                fma2(acc[ii][hh], av[ii].x, wv[hh].x);
                fma2(acc[ii][hh], av[ii].y, wv[hh].y);
            }
    }

    #pragma unroll
    for (int ii = 0; ii < 4; ii++){
        int r = ty + 16*ii;
        #pragma unroll
        for (int hh = 0; hh < 4; hh++){
            int c = tx + 16*hh;
            float v = flo(acc[ii][hh]) + fhi(acc[ii][hh]) + sB[c];
            dst[r*128 + gy*64 + c] = fmaxf(v, 0.0f);
        }
    }
}

// ============================================================================
// Fused flash attention (fp32, FFMA2):
//   S = Xp(64x128) . Yp^T (64-j tiles), masked online softmax, O += P . y_tile.
// P (duplicated f32x2) overlays the dead Yp smem buffer between phases.
// grid: (16 i-tiles, 64 batches), 256 threads, 2 CTAs/SM (96.25 KB smem).
// ============================================================================
__global__ __launch_bounds__(256, 2) void attn_kernel(
    const float* __restrict__ yg, const int* __restrict__ ymask, float* __restrict__ out)
{
    extern __shared__ __align__(16) float smem[];
    float* sXp   = smem;            // [64][128] plain
    float* sYp   = smem + 8192;     // [64][128] swizzled; later overlaid by P2 [64][64] u64
    float* sY    = smem + 16384;    // [64][128] plain
    float* sMask = smem + 24576;    // [64] additive mask (0 or -1e30)

    const int b = blockIdx.y, it = blockIdx.x;
    const int tid = threadIdx.x, tx = tid & 15, ty = tid >> 4;

    const float4* xp4 = (const float4*)(g_xp + ((size_t)b*1024 + it*64) * 128);
    const float*  ypB = g_yp + (size_t)b * 131072;
    const float*  yB  = yg   + (size_t)b * 131072;
    const int*    mB  = ymask + b * 1024;

    for (int f = tid; f < 2048; f += 256) ((float4*)sXp)[f] = xp4[f];

    unsigned long long O2[4][4];
    #pragma unroll
    for (int i = 0; i < 4; i++)
        #pragma unroll
        for (int k = 0; k < 4; k++) O2[i][k] = 0ull;
    float m[4], l[4];
    #pragma unroll
    for (int i = 0; i < 4; i++){ m[i] = -3.0e38f; l[i] = 0.0f; }

    for (int jt = 0; jt < 16; jt++){
        __syncthreads();   // previous O-phase done reading sY / P2 before overwrite
        const float4* yp4 = (const float4*)(ypB + jt*8192);
        const float4* y4  = (const float4*)(yB  + jt*8192);
        for (int f = tid; f < 2048; f += 256){
            int j = f >> 5, d4 = f & 31;
            ((float4*)sYp)[(j << 5) + (d4 ^ (j & 7))] = yp4[f];
            ((float4*)sY)[f] = y4[f];
        }
        if (tid < 64) sMask[tid] = mB[jt*64 + tid] ? -1.0e30f : 0.0f;
        __syncthreads();

        // ---- S = Xp . Yp^T (d-paired f32x2 partial sums) ----
        unsigned long long S2[4][4];
        #pragma unroll
        for (int i = 0; i < 4; i++)
            #pragma unroll
            for (int k = 0; k < 4; k++) S2[i][k] = 0ull;

        #pragma unroll 8
        for (int d4 = 0; d4 < 32; d4++){
            ulonglong2 av[4], bv[4];
            #pragma unroll
            for (int ii = 0; ii < 4; ii++)
                av[ii] = ((const ulonglong2*)sXp)[((ty + 16*ii) << 5) + d4];
            #pragma unroll
            for (int jj = 0; jj < 4; jj++){
                int j = tx + 16*jj;
                bv[jj] = ((const ulonglong2*)sYp)[(j << 5) + (d4 ^ (j & 7))];
            }
            #pragma unroll
            for (int ii = 0; ii < 4; ii++)
                #pragma unroll
                for (int jj = 0; jj < 4; jj++){
                    fma2(S2[ii][jj], av[ii].x, bv[jj].x);
                    fma2(S2[ii][jj], av[ii].y, bv[jj].y);
                }
        }

        // ---- mask + online softmax ----
        float Sv[4][4], mt[4];
        #pragma unroll
        for (int ii = 0; ii < 4; ii++){
            #pragma unroll
            for (int jj = 0; jj < 4; jj++)
                Sv[ii][jj] = flo(S2[ii][jj]) + fhi(S2[ii][jj]) + sMask[tx + 16*jj];
            mt[ii] = fmaxf(fmaxf(Sv[ii][0], Sv[ii][1]), fmaxf(Sv[ii][2], Sv[ii][3]));
        }
        #pragma unroll
        for (int o = 1; o < 16; o <<= 1)
            #pragma unroll
            for (int ii = 0; ii < 4; ii++)
                mt[ii] = fmaxf(mt[ii], __shfl_xor_sync(0xffffffffu, mt[ii], o));

        float sc[4], rs[4], P[4][4];
        #pragma unroll
        for (int ii = 0; ii < 4; ii++){
            float mn = fmaxf(m[ii], mt[ii]);
            sc[ii] = __expf(m[ii] - mn);
            m[ii] = mn;
            rs[ii] = 0.0f;
            #pragma unroll
            for (int jj = 0; jj < 4; jj++){
                P[ii][jj] = __expf(Sv[ii][jj] - mn);
                rs[ii] += P[ii][jj];
            }
        }
        #pragma unroll
        for (int o = 1; o < 16; o <<= 1)
            #pragma unroll
            for (int ii = 0; ii < 4; ii++)
                rs[ii] += __shfl_xor_sync(0xffffffffu, rs[ii], o);
        #pragma unroll
        for (int ii = 0; ii < 4; ii++){
            l[ii] = l[ii]*sc[ii] + rs[ii];
            unsigned long long s2 = fdup(sc[ii]);
            #pragma unroll
            for (int k = 0; k < 4; k++) mul2(O2[ii][k], s2);
        }

        __syncthreads();   // all S-phase reads of sYp done
        unsigned long long* P2 = (unsigned long long*)sYp;   // [64][64] duplicated-f32x2
        #pragma unroll
        for (int ii = 0; ii < 4; ii++)
            #pragma unroll
            for (int jj = 0; jj < 4; jj++)
                P2[((ty + 16*ii) << 6) + tx + 16*jj] = fdup(P[ii][jj]);
        __syncthreads();

        // ---- O += P . y_tile (h-paired f32x2, P pre-duplicated) ----
        #pragma unroll 4
        for (int j = 0; j < 64; j++){
            ulonglong2 b0 = ((const ulonglong2*)sY)[(j << 5) + tx];        // cols 4tx..4tx+3
            ulonglong2 b1 = ((const ulonglong2*)sY)[(j << 5) + 16 + tx];   // cols 64+4tx..
            #pragma unroll
            for (int ii = 0; ii < 4; ii++){
                unsigned long long a = P2[((ty + 16*ii) << 6) + j];
                fma2(O2[ii][0], a, b0.x);
                fma2(O2[ii][1], a, b0.y);
                fma2(O2[ii][2], a, b1.x);
                fma2(O2[ii][3], a, b1.y);
            }
        }
    }

    // ---- epilogue: O / l, coalesced float4 stores ----
    float* outB = out + ((size_t)b*1024 + it*64) * 128;
    #pragma unroll
    for (int ii = 0; ii < 4; ii++){
        float inv = 1.0f / l[ii];
        int r = ty + 16*ii;
        float4 v0, v1;
        v0.x = flo(O2[ii][0])*inv; v0.y = fhi(O2[ii][0])*inv;
        v0.z = flo(O2[ii][1])*inv; v0.w = fhi(O2[ii][1])*inv;
        v1.x = flo(O2[ii][2])*inv; v1.y = fhi(O2[ii][2])*inv;
        v1.z = flo(O2[ii][3])*inv; v1.w = fhi(O2[ii][3])*inv;
        ((float4*)(outB + r*128))[tx]      = v0;
        ((float4*)(outB + r*128))[16 + tx] = v1;
    }
}

extern "C" void kernel_launch(void* const* d_in, const int* in_sizes, int n_in,
                              void* d_out, int out_size)
{
    const float* x    = (const float*)d_in[0];
    const float* y    = (const float*)d_in[1];
    const int*   ym   = (const int*)d_in[2];   // y_mask: nonzero = padded
    const float* W    = (const float*)d_in[3];
    const float* bias = (const float*)d_in[4];
    float* out = (float*)d_out;

    const int projSmem = (8192 + 8192 + 64) * 4;          // 65792 B
    const int attnSmem = (3*8192 + 64) * 4;               // 98560 B
    cudaFuncSetAttribute(proj_kernel, cudaFuncAttributeMaxDynamicSharedMemorySize, projSmem);
    cudaFuncSetAttribute(attn_kernel, cudaFuncAttributeMaxDynamicSharedMemorySize, attnSmem);

    proj_kernel<<<dim3(2048, 2), 256, projSmem>>>(x, y, W, bias);
    attn_kernel<<<dim3(16, 64), 256, attnSmem>>>(y, ym, out);
}